// round 4
// baseline (speedup 1.0000x reference)
#include <cuda_runtime.h>
#include <cstddef>

#define BATCH 32
#define NUU   64
#define NYY   64
#define NXX   512
#define NWW   512
#define TSTEP 1024
#define RCTAS 128
#define RTHR  256
#define GRPC  64      // CTAs per group
#define BG    16      // batches per group
#define ARRS  128     // arrivals per phase per group (2 per CTA * 64)
#define PST   66      // partial-buffer stride in u64 (bank-stagger)

typedef unsigned long long u64;

// ---------------- packed f32x2 helpers ----------------------------------------
#define FMA2(acc, w, h) asm("fma.rn.f32x2 %0, %1, %2, %0;" : "+l"(acc) : "l"(w), "l"(h))
#define ADD2(acc, v)    asm("add.rn.f32x2 %0, %0, %1;"     : "+l"(acc) : "l"(v))
__device__ __forceinline__ u64 pack2(float a, float b) {
    u64 r;
    asm("mov.b64 %0, {%1, %2};" : "=l"(r) : "r"(__float_as_uint(a)), "r"(__float_as_uint(b)));
    return r;
}
__device__ __forceinline__ void unpack2(u64 v, float& a, float& b) {
    unsigned lo, hi;
    asm("mov.b64 {%0, %1}, %2;" : "=r"(lo), "=r"(hi) : "l"(v));
    a = __uint_as_float(lo); b = __uint_as_float(hi);
}

// ---------------- device scratch ----------------------------------------------
__device__ float d_Cv[NWW * NXX];
__device__ float d_Dv[NWW * NUU];
__device__ float d_X[NXX * NXX];
__device__ float d_X2[NXX * NXX];
__device__ float d_T1[NXX * NXX];
__device__ float d_Ahat[NXX * NXX];
__device__ float d_Bhat[NXX * NWW];
__device__ float d_B2hat[NXX * NUU];
__device__ float d_fbhat[NXX];
__device__ float d_G1[(size_t)TSTEP * BATCH * NWW];     // [t][b][j]
__device__ float d_G2[(size_t)TSTEP * BATCH * NXX];     // [t][b][x]
__device__ float d_states[(size_t)TSTEP * BATCH * NXX]; // [t][b][x]
__device__ float d_Wb[(size_t)TSTEP * BATCH * NWW];     // [t][b][j]
__device__ float d_hbuf[2 * NXX * BG];  // [g][x][b16]
__device__ float d_wvec[2 * NWW * BG];  // [g][j][b16]
__device__ unsigned g_cnt[2];

// ---------------- barrier primitives ------------------------------------------
__device__ __forceinline__ void bar_arrive(unsigned* cnt) {
    asm volatile("red.release.gpu.add.u32 [%0], 1;" :: "l"(cnt) : "memory");
}
__device__ __forceinline__ void wait_cnt(unsigned* cnt, unsigned target) {
    unsigned v;
    do {
        asm volatile("ld.acquire.gpu.u32 %0, [%1];" : "=r"(v) : "l"(cnt) : "memory");
    } while (v < target);
}

// ---------------- prep: Cv, Dv, X0 = 2I - E -----------------------------------
__global__ void prep_kernel(const float* __restrict__ C2, const float* __restrict__ mult,
                            const float* __restrict__ Dt, const float* __restrict__ E) {
    int i = blockIdx.x * blockDim.x + threadIdx.x;
    int stride = gridDim.x * blockDim.x;
    for (int idx = i; idx < NWW * NXX; idx += stride) {
        int r = idx / NXX;
        d_Cv[idx] = C2[idx] / mult[r];
    }
    for (int idx = i; idx < NWW * NUU; idx += stride) {
        int r = idx / NUU;
        d_Dv[idx] = Dt[idx] / mult[r];
    }
    for (int idx = i; idx < NXX * NXX; idx += stride) {
        int r = idx / NXX, c = idx % NXX;
        d_X[idx] = (r == c ? 2.0f : 0.0f) - E[idx];
    }
}

// ---------------- fp32 tiled GEMM (double buffered); mode1: C = 2I - A@B ------
__global__ void gemm_rrr(const float* __restrict__ A, const float* __restrict__ Bm,
                         float* __restrict__ C, int M, int N, int K, int mode) {
    __shared__ float As[2][16][64];
    __shared__ float Bs[2][16][64];
    int tid = threadIdx.x;
    int tx = tid & 15, ty = tid >> 4;
    int bx = blockIdx.x, by = blockIdx.y;
    int ar = tid >> 2, ac = (tid & 3) << 2;
    int br = tid >> 4, bc = (tid & 15) << 2;
    const float* Aptr = A + (size_t)(by * 64 + ar) * K + ac;
    const float* Bptr = Bm + (size_t)br * N + bx * 64 + bc;

    float4 av = *(const float4*)Aptr;
    float4 bv = *(const float4*)Bptr;
    As[0][ac + 0][ar] = av.x; As[0][ac + 1][ar] = av.y;
    As[0][ac + 2][ar] = av.z; As[0][ac + 3][ar] = av.w;
    *(float4*)&Bs[0][br][bc] = bv;
    __syncthreads();

    float acc[4][4] = {};
    int buf = 0;
    for (int k0 = 16; k0 <= K; k0 += 16) {
        if (k0 < K) {
            av = *(const float4*)(Aptr + k0);
            bv = *(const float4*)(Bptr + (size_t)k0 * N);
        }
#pragma unroll
        for (int k = 0; k < 16; k++) {
            float4 a = *(const float4*)&As[buf][k][ty * 4];
            float4 b = *(const float4*)&Bs[buf][k][tx * 4];
            acc[0][0] = fmaf(a.x, b.x, acc[0][0]); acc[0][1] = fmaf(a.x, b.y, acc[0][1]);
            acc[0][2] = fmaf(a.x, b.z, acc[0][2]); acc[0][3] = fmaf(a.x, b.w, acc[0][3]);
            acc[1][0] = fmaf(a.y, b.x, acc[1][0]); acc[1][1] = fmaf(a.y, b.y, acc[1][1]);
            acc[1][2] = fmaf(a.y, b.z, acc[1][2]); acc[1][3] = fmaf(a.y, b.w, acc[1][3]);
            acc[2][0] = fmaf(a.z, b.x, acc[2][0]); acc[2][1] = fmaf(a.z, b.y, acc[2][1]);
            acc[2][2] = fmaf(a.z, b.z, acc[2][2]); acc[2][3] = fmaf(a.z, b.w, acc[2][3]);
            acc[3][0] = fmaf(a.w, b.x, acc[3][0]); acc[3][1] = fmaf(a.w, b.y, acc[3][1]);
            acc[3][2] = fmaf(a.w, b.z, acc[3][2]); acc[3][3] = fmaf(a.w, b.w, acc[3][3]);
        }
        if (k0 < K) {
            int nb = buf ^ 1;
            As[nb][ac + 0][ar] = av.x; As[nb][ac + 1][ar] = av.y;
            As[nb][ac + 2][ar] = av.z; As[nb][ac + 3][ar] = av.w;
            *(float4*)&Bs[nb][br][bc] = bv;
        }
        __syncthreads();
        buf ^= 1;
    }
#pragma unroll
    for (int i = 0; i < 4; i++) {
        int r = by * 64 + ty * 4 + i;
        float o[4];
#pragma unroll
        for (int j = 0; j < 4; j++) {
            int cx = bx * 64 + tx * 4 + j;
            float v = acc[i][j];
            if (mode) v = (r == cx ? 2.0f : 0.0f) - v;
            o[j] = v;
        }
        *(float4*)&C[(size_t)r * N + bx * 64 + tx * 4] = make_float4(o[0], o[1], o[2], o[3]);
    }
}

// fbhat = Einv @ v
__global__ void matvec_kernel(const float* __restrict__ Einv, const float* __restrict__ v) {
    int r = blockIdx.x * blockDim.x + threadIdx.x;
    if (r < NXX) {
        float s = 0.f;
        for (int k = 0; k < NXX; k++) s = fmaf(Einv[(size_t)r * NXX + k], v[k], s);
        d_fbhat[r] = s;
    }
}

// ---------------- u projections: out[(t*B + b)*J + j] -------------------------
__global__ void uproj_kernel(const float* __restrict__ u, const float* __restrict__ M,
                             const float* __restrict__ bias, float* __restrict__ out, int J) {
    __shared__ float U_s[NUU][65];
    __shared__ float M_s[64][65];
    int tid = threadIdx.x;
    int j0 = blockIdx.x * 64, t0 = blockIdx.y * 64, b = blockIdx.z;
    for (int i = tid; i < 64 * 64; i += 256) {
        int kk = i >> 6, tt = i & 63;
        U_s[kk][tt] = u[(size_t)b * NUU * TSTEP + (size_t)kk * TSTEP + t0 + tt];
    }
    for (int i = tid; i < 64 * 64; i += 256) {
        int j = i >> 6, k = i & 63;
        M_s[j][k] = M[(size_t)(j0 + j) * NUU + k];
    }
    __syncthreads();
    int lane = tid & 31, wg = tid >> 5;
    float acc0[8] = {}, acc1[8] = {};
    for (int k = 0; k < 64; k++) {
        float u0 = U_s[k][lane], u1 = U_s[k][lane + 32];
#pragma unroll
        for (int j = 0; j < 8; j++) {
            float m = M_s[wg * 8 + j][k];
            acc0[j] = fmaf(u0, m, acc0[j]);
            acc1[j] = fmaf(u1, m, acc1[j]);
        }
    }
    int jj0 = j0 + wg * 8;
    float bsv[8];
#pragma unroll
    for (int j = 0; j < 8; j++) bsv[j] = bias[jj0 + j];
    size_t r0 = ((size_t)(t0 + lane) * BATCH + b) * J + jj0;
    size_t r1 = ((size_t)(t0 + lane + 32) * BATCH + b) * J + jj0;
    *(float4*)&out[r0]     = make_float4(acc0[0] + bsv[0], acc0[1] + bsv[1], acc0[2] + bsv[2], acc0[3] + bsv[3]);
    *(float4*)&out[r0 + 4] = make_float4(acc0[4] + bsv[4], acc0[5] + bsv[5], acc0[6] + bsv[6], acc0[7] + bsv[7]);
    *(float4*)&out[r1]     = make_float4(acc1[0] + bsv[0], acc1[1] + bsv[1], acc1[2] + bsv[2], acc1[3] + bsv[3]);
    *(float4*)&out[r1 + 4] = make_float4(acc1[4] + bsv[4], acc1[5] + bsv[5], acc1[6] + bsv[6], acc1[7] + bsv[7]);
}

// ---------------- init --------------------------------------------------------
__global__ void init_kernel() {
    int i = blockIdx.x * blockDim.x + threadIdx.x;
    int stride = gridDim.x * blockDim.x;
    if (i == 0) { g_cnt[0] = 0u; g_cnt[1] = 0u; }
    for (int idx = i; idx < 2 * NXX * BG; idx += stride) d_hbuf[idx] = 0.f;
    for (int idx = i; idx < BATCH * NXX; idx += stride) d_states[idx] = 0.f;
}

// ---------------- packed dot: 8 rows x 16 k, one batch-pair -------------------
// hp: state [k][b], stride BG; w64: duplicated weights [k][8 rows] u64
__device__ __forceinline__ void dot16(const float* __restrict__ hp,
                                      const u64* __restrict__ w64, u64* acc) {
#pragma unroll
    for (int kk = 0; kk < 16; kk++) {
        u64 hv2 = *(const u64*)(hp + kk * BG);
        const ulonglong2* wq = (const ulonglong2*)(w64 + kk * 8);
        ulonglong2 wa = wq[0], wb = wq[1], wc = wq[2], wd = wq[3];
        FMA2(acc[0], wa.x, hv2); FMA2(acc[1], wa.y, hv2);
        FMA2(acc[2], wb.x, hv2); FMA2(acc[3], wb.y, hv2);
        FMA2(acc[4], wc.x, hv2); FMA2(acc[5], wc.y, hv2);
        FMA2(acc[6], wd.x, hv2); FMA2(acc[7], wd.y, hv2);
    }
}

__device__ __forceinline__ u64 sum32(const u64* __restrict__ base, int off, u64 init) {
    u64 s0 = init, s1 = 0ull;
#pragma unroll
    for (int p = 0; p < 32; p += 2) {
        ADD2(s0, base[p * PST + off]);
        ADD2(s1, base[(p + 1) * PST + off]);
    }
    ADD2(s0, s1);
    return s0;
}

// ---------------- persistent sequential recurrence ----------------------------
// smem: wC/wA/wB dup-weights 3*4096 u64 | h_s,w_s 8192 f32 each | pW/pA/pB 32*PST u64 each
__global__ void __launch_bounds__(RTHR, 1) recur_kernel() {
    extern __shared__ u64 smem64[];
    u64*   wC  = smem64;
    u64*   wA  = wC + 4096;
    u64*   wB  = wA + 4096;
    float* h_s = (float*)(wB + 4096);
    float* w_s = h_s + NXX * BG;
    u64*   pW  = (u64*)(w_s + NWW * BG);
    u64*   pA  = pW + 32 * PST;
    u64*   pB  = pA + 32 * PST;

    int tid  = threadIdx.x;
    int cta  = blockIdx.x;
    int g    = cta >> 6;
    int j0   = (cta & 63) * 8;
    int warp = tid >> 5, lane = tid & 31;
    int kh = lane >> 3, b2 = lane & 7;          // dot mapping
    int rrow = tid >> 3, rb2 = tid & 7;         // reduce mapping (tid<64)

    float* hg = d_hbuf + g * NXX * BG;
    float* wg = d_wvec + g * NWW * BG;
    unsigned* cnt = &g_cnt[g];

    // stage duplicated weight slices
    for (int i = tid; i < 4096; i += RTHR) {
        int k = i >> 3, c = i & 7;
        float vc = d_Cv[(size_t)(j0 + c) * NXX + k];
        float va = d_Ahat[(size_t)(j0 + c) * NXX + k];
        float vb = d_Bhat[(size_t)(j0 + c) * NWW + k];
        wC[i] = pack2(vc, vc);
        wA[i] = pack2(va, va);
        wB[i] = pack2(vb, vb);
    }
    __syncthreads();

    int ksub = warp * 64 + kh * 16;
    const float* hpp = h_s + ksub * BG + 2 * b2;
    const float* wpp = w_s + ksub * BG + 2 * b2;
    u64* ppW = pW + (warp * 4 + kh) * PST + b2;
    u64* ppA = pA + (warp * 4 + kh) * PST + b2;
    u64* ppB = pB + (warp * 4 + kh) * PST + b2;
    int roff = rrow * 8 + rb2;
    int bb = g * BG + 2 * rb2;

    for (int t = 0; t < TSTEP; t++) {
        // prefetch G terms (reduce warps), in flight during spin
        u64 g1v = 0ull, g2v = 0ull;
        if (tid < 64) {
            const float* p1 = &d_G1[((size_t)t * BATCH + bb) * NWW + j0 + rrow];
            g1v = pack2(__ldcg(p1), __ldcg(p1 + NWW));
            if (t < TSTEP - 1) {
                const float* p2 = &d_G2[((size_t)t * BATCH + bb) * NXX + j0 + rrow];
                g2v = pack2(__ldcg(p2), __ldcg(p2 + NXX));
            }
        }
        // wait h(t) ready
        if (t > 0) wait_cnt(cnt, (unsigned)(2 * t) * ARRS);
        // per-warp copy of own 64-k chunk of h
        {
            const float4* src = (const float4*)hg + warp * 256;
            float4* dst = (float4*)h_s + warp * 256;
#pragma unroll
            for (int i = 0; i < 8; i++) dst[lane + 32 * i] = __ldcg(&src[lane + 32 * i]);
        }
        __syncwarp();
        // phase A: Cv @ h
        {
            u64 acc[8] = {};
            dot16(hpp, wC + ksub * 8, acc);
#pragma unroll
            for (int c = 0; c < 8; c++) ppW[c * 8] = acc[c];
        }
        __syncthreads();  // #1: pW complete
        if (tid < 64) {
            u64 s = sum32(pW, roff, g1v);
            float lo, hi;
            unpack2(s, lo, hi);
            lo = fmaxf(lo, 0.f); hi = fmaxf(hi, 0.f);
            wg[(j0 + rrow) * BG + 2 * rb2] = lo;
            wg[(j0 + rrow) * BG + 2 * rb2 + 1] = hi;
            float* wbp = &d_Wb[((size_t)t * BATCH + bb) * NWW + j0 + rrow];
            wbp[0] = lo; wbp[NWW] = hi;
        }
        if (t == TSTEP - 1) break;
        if (tid < 64) {
            __syncwarp();
            if ((tid & 31) == 0) bar_arrive(cnt);   // w(t) ready
        }
        // Ahat @ h (hides w barrier)
        {
            u64 acc[8] = {};
            dot16(hpp, wA + ksub * 8, acc);
#pragma unroll
            for (int c = 0; c < 8; c++) ppA[c * 8] = acc[c];
        }
        // wait w(t)
        wait_cnt(cnt, (unsigned)(2 * t + 1) * ARRS);
        {
            const float4* src = (const float4*)wg + warp * 256;
            float4* dst = (float4*)w_s + warp * 256;
#pragma unroll
            for (int i = 0; i < 8; i++) dst[lane + 32 * i] = __ldcg(&src[lane + 32 * i]);
        }
        __syncwarp();
        // Bhat @ w
        {
            u64 acc[8] = {};
            dot16(wpp, wB + ksub * 8, acc);
#pragma unroll
            for (int c = 0; c < 8; c++) ppB[c * 8] = acc[c];
        }
        __syncthreads();  // #2: pA,pB complete
        if (tid < 64) {
            u64 s = sum32(pA, roff, g2v);
            s = sum32(pB, roff, s);
            hg[(j0 + rrow) * BG + 2 * rb2]     = ((float2*)&s)->x;
            hg[(j0 + rrow) * BG + 2 * rb2 + 1] = ((float2*)&s)->y;
            float lo, hi;
            unpack2(s, lo, hi);
            float* stp = &d_states[((size_t)(t + 1) * BATCH + bb) * NXX + j0 + rrow];
            stp[0] = lo; stp[NXX] = hi;
            __syncwarp();
            if ((tid & 31) == 0) bar_arrive(cnt);   // h(t+1) ready
        }
    }
}

// ---------------- epilogue ----------------------------------------------------
__global__ void yfinal_kernel(const float* __restrict__ u, const float* __restrict__ C1,
                              const float* __restrict__ D11, const float* __restrict__ D12,
                              const float* __restrict__ by, float* __restrict__ out) {
    __shared__ float As[64][65];
    __shared__ float Bs[64][68];
    int tid = threadIdx.x;
    int tx = tid & 15, ty = tid >> 4;
    int t0 = blockIdx.x * 64, b = blockIdx.y;
    float acc[4][4] = {};
    for (int seg = 0; seg < 3; seg++) {
        int nchunk = (seg == 2) ? 1 : 8;
        const float* Am = (seg == 0) ? C1 : (seg == 1) ? D11 : D12;
        int Ksz = (seg == 2) ? 64 : 512;
        for (int ch = 0; ch < nchunk; ch++) {
            int x0 = ch * 64;
            for (int i = tid; i < 64 * 64; i += 256) {
                int j = i >> 6, k = i & 63;
                As[j][k] = Am[(size_t)j * Ksz + x0 + k];
            }
            if (seg == 2) {
                for (int i = tid; i < 64 * 64; i += 256) {
                    int k = i >> 6, tt = i & 63;
                    Bs[k][tt] = u[((size_t)b * NUU + k) * TSTEP + t0 + tt];
                }
            } else {
                const float* S = (seg == 0) ? d_states : d_Wb;
                for (int i = tid; i < 64 * 64; i += 256) {
                    int tt = i >> 6, xx = i & 63;
                    Bs[xx][tt] = S[((size_t)(t0 + tt) * BATCH + b) * 512 + x0 + xx];
                }
            }
            __syncthreads();
#pragma unroll 8
            for (int k = 0; k < 64; k++) {
                float a0 = As[ty * 4 + 0][k];
                float a1 = As[ty * 4 + 1][k];
                float a2 = As[ty * 4 + 2][k];
                float a3 = As[ty * 4 + 3][k];
                float4 bv = *(const float4*)&Bs[k][tx * 4];
                acc[0][0] = fmaf(a0, bv.x, acc[0][0]); acc[0][1] = fmaf(a0, bv.y, acc[0][1]);
                acc[0][2] = fmaf(a0, bv.z, acc[0][2]); acc[0][3] = fmaf(a0, bv.w, acc[0][3]);
                acc[1][0] = fmaf(a1, bv.x, acc[1][0]); acc[1][1] = fmaf(a1, bv.y, acc[1][1]);
                acc[1][2] = fmaf(a1, bv.z, acc[1][2]); acc[1][3] = fmaf(a1, bv.w, acc[1][3]);
                acc[2][0] = fmaf(a2, bv.x, acc[2][0]); acc[2][1] = fmaf(a2, bv.y, acc[2][1]);
                acc[2][2] = fmaf(a2, bv.z, acc[2][2]); acc[2][3] = fmaf(a2, bv.w, acc[2][3]);
                acc[3][0] = fmaf(a3, bv.x, acc[3][0]); acc[3][1] = fmaf(a3, bv.y, acc[3][1]);
                acc[3][2] = fmaf(a3, bv.z, acc[3][2]); acc[3][3] = fmaf(a3, bv.w, acc[3][3]);
            }
            __syncthreads();
        }
    }
#pragma unroll
    for (int i = 0; i < 4; i++) {
        int j = ty * 4 + i;
        float bj = by[j];
        float4 o = make_float4(acc[i][0] + bj, acc[i][1] + bj, acc[i][2] + bj, acc[i][3] + bj);
        *(float4*)&out[((size_t)b * NYY + j) * TSTEP + t0 + tx * 4] = o;
    }
}

// ---------------- launch ------------------------------------------------------
extern "C" void kernel_launch(void* const* d_in, const int* in_sizes, int n_in,
                              void* d_out, int out_size) {
    const float* u      = (const float*)d_in[0];
    const float* E      = (const float*)d_in[1];
    const float* F_w    = (const float*)d_in[2];
    const float* F_b    = (const float*)d_in[3];
    const float* B1_w   = (const float*)d_in[4];
    const float* B2_w   = (const float*)d_in[5];
    const float* C2tild = (const float*)d_in[6];
    const float* bv     = (const float*)d_in[7];
    const float* Dtild  = (const float*)d_in[8];
    const float* C1_w   = (const float*)d_in[9];
    const float* D11_w  = (const float*)d_in[10];
    const float* D12_w  = (const float*)d_in[11];
    const float* by     = (const float*)d_in[12];
    const float* multis = (const float*)d_in[13];
    float* out = (float*)d_out;

    float *X, *X2, *T1, *Ahat, *Bhat, *B2hat, *Dv, *G1, *G2, *fbhat;
    cudaGetSymbolAddress((void**)&X,     d_X);
    cudaGetSymbolAddress((void**)&X2,    d_X2);
    cudaGetSymbolAddress((void**)&T1,    d_T1);
    cudaGetSymbolAddress((void**)&Ahat,  d_Ahat);
    cudaGetSymbolAddress((void**)&Bhat,  d_Bhat);
    cudaGetSymbolAddress((void**)&B2hat, d_B2hat);
    cudaGetSymbolAddress((void**)&Dv,    d_Dv);
    cudaGetSymbolAddress((void**)&G1,    d_G1);
    cudaGetSymbolAddress((void**)&G2,    d_G2);
    cudaGetSymbolAddress((void**)&fbhat, d_fbhat);

    // 3*4096 u64 + 2*8192 f32 + 3*32*PST u64
    const int SMEM_RECUR = 3 * 4096 * 8 + 2 * 8192 * 4 + 3 * 32 * PST * 8;
    cudaFuncSetAttribute(recur_kernel, cudaFuncAttributeMaxDynamicSharedMemorySize, SMEM_RECUR);

    prep_kernel<<<256, 256>>>(C2tild, multis, Dtild, E);

    dim3 g88(8, 8);
    for (int it = 0; it < 4; it++) {
        gemm_rrr<<<g88, 256>>>(E, X, T1, 512, 512, 512, 1);   // T1 = 2I - E@X
        gemm_rrr<<<g88, 256>>>(X, T1, X2, 512, 512, 512, 0);
        float* tmp = X; X = X2; X2 = tmp;
    }

    gemm_rrr<<<g88, 256>>>(X, F_w, Ahat, 512, 512, 512, 0);
    gemm_rrr<<<g88, 256>>>(X, B1_w, Bhat, 512, 512, 512, 0);
    gemm_rrr<<<dim3(1, 8), 256>>>(X, B2_w, B2hat, 512, 64, 512, 0);
    matvec_kernel<<<2, 256>>>(X, F_b);

    uproj_kernel<<<dim3(8, 16, 32), 256>>>(u, Dv, bv, G1, NWW);
    uproj_kernel<<<dim3(8, 16, 32), 256>>>(u, B2hat, fbhat, G2, NXX);

    init_kernel<<<64, 256>>>();
    recur_kernel<<<RCTAS, RTHR, SMEM_RECUR>>>();

    yfinal_kernel<<<dim3(16, 32), 256>>>(u, C1_w, D11_w, D12_w, by, out);
}

// round 5
// speedup vs baseline: 2.1066x; 2.1066x over previous
#include <cuda_runtime.h>
#include <cstddef>

#define BATCH 32
#define NUU   64
#define NYY   64
#define NXX   512
#define NWW   512
#define TSTEP 1024
#define RCTAS 128
#define RTHR  256
#define GROUPS 4
#define GCTAS 32     // CTAs per group
#define BGS   8      // batches per group
#define ROWS  16     // rows per CTA
#define PST   136    // partial-buffer stride (floats)

// ---------------- device scratch (__device__ globals: allocation-free) --------
__device__ float d_Cv[NWW * NXX];
__device__ float d_Dv[NWW * NUU];
__device__ float d_X[NXX * NXX];
__device__ float d_X2[NXX * NXX];
__device__ float d_T1[NXX * NXX];
__device__ float d_Ahat[NXX * NXX];
__device__ float d_Bhat[NXX * NWW];
__device__ float d_B2hat[NXX * NUU];
__device__ float d_fbhat[NXX];
__device__ float d_G1[(size_t)TSTEP * BATCH * NWW];     // [t][b][j]
__device__ float d_G2[(size_t)TSTEP * BATCH * NXX];     // [t][b][x]
__device__ float d_states[(size_t)TSTEP * BATCH * NXX]; // [t][b][x]
__device__ float d_Wb[(size_t)TSTEP * BATCH * NWW];     // [t][b][j]
__device__ float d_hbuf[GROUPS * NXX * BGS];  // [g][x][b8]
__device__ float d_wvec[GROUPS * NWW * BGS];  // [g][j][b8]
__device__ unsigned g_cnt[GROUPS * 32];       // 128B-padded counters

// ---------------- barrier primitives ------------------------------------------
__device__ __forceinline__ void bar_arrive(unsigned* cnt) {
    asm volatile("red.release.gpu.add.u32 [%0], 1;" :: "l"(cnt) : "memory");
}
__device__ __forceinline__ void wait_cnt(unsigned* cnt, unsigned target) {
    unsigned v;
    do {
        asm volatile("ld.acquire.gpu.u32 %0, [%1];" : "=r"(v) : "l"(cnt) : "memory");
    } while (v < target);
}
__device__ __forceinline__ float4 ldcg4(const float4* p) {
    float4 v;
    asm volatile("ld.global.cg.v4.f32 {%0,%1,%2,%3}, [%4];"
                 : "=f"(v.x), "=f"(v.y), "=f"(v.z), "=f"(v.w) : "l"(p));
    return v;
}

// ---------------- prep: Cv, Dv, X0 = 2I - E -----------------------------------
__global__ void prep_kernel(const float* __restrict__ C2, const float* __restrict__ mult,
                            const float* __restrict__ Dt, const float* __restrict__ E) {
    int i = blockIdx.x * blockDim.x + threadIdx.x;
    int stride = gridDim.x * blockDim.x;
    for (int idx = i; idx < NWW * NXX; idx += stride) {
        int r = idx / NXX;
        d_Cv[idx] = C2[idx] / mult[r];
    }
    for (int idx = i; idx < NWW * NUU; idx += stride) {
        int r = idx / NUU;
        d_Dv[idx] = Dt[idx] / mult[r];
    }
    for (int idx = i; idx < NXX * NXX; idx += stride) {
        int r = idx / NXX, c = idx % NXX;
        d_X[idx] = (r == c ? 2.0f : 0.0f) - E[idx];
    }
}

// ---------------- fp32 tiled GEMM (double buffered); mode1: C = 2I - A@B ------
__global__ void gemm_rrr(const float* __restrict__ A, const float* __restrict__ Bm,
                         float* __restrict__ C, int M, int N, int K, int mode) {
    __shared__ float As[2][16][64];
    __shared__ float Bs[2][16][64];
    int tid = threadIdx.x;
    int tx = tid & 15, ty = tid >> 4;
    int bx = blockIdx.x, by = blockIdx.y;
    int ar = tid >> 2, ac = (tid & 3) << 2;
    int br = tid >> 4, bc = (tid & 15) << 2;
    const float* Aptr = A + (size_t)(by * 64 + ar) * K + ac;
    const float* Bptr = Bm + (size_t)br * N + bx * 64 + bc;

    float4 av = *(const float4*)Aptr;
    float4 bv = *(const float4*)Bptr;
    As[0][ac + 0][ar] = av.x; As[0][ac + 1][ar] = av.y;
    As[0][ac + 2][ar] = av.z; As[0][ac + 3][ar] = av.w;
    *(float4*)&Bs[0][br][bc] = bv;
    __syncthreads();

    float acc[4][4] = {};
    int buf = 0;
    for (int k0 = 16; k0 <= K; k0 += 16) {
        if (k0 < K) {
            av = *(const float4*)(Aptr + k0);
            bv = *(const float4*)(Bptr + (size_t)k0 * N);
        }
#pragma unroll
        for (int k = 0; k < 16; k++) {
            float4 a = *(const float4*)&As[buf][k][ty * 4];
            float4 b = *(const float4*)&Bs[buf][k][tx * 4];
            acc[0][0] = fmaf(a.x, b.x, acc[0][0]); acc[0][1] = fmaf(a.x, b.y, acc[0][1]);
            acc[0][2] = fmaf(a.x, b.z, acc[0][2]); acc[0][3] = fmaf(a.x, b.w, acc[0][3]);
            acc[1][0] = fmaf(a.y, b.x, acc[1][0]); acc[1][1] = fmaf(a.y, b.y, acc[1][1]);
            acc[1][2] = fmaf(a.y, b.z, acc[1][2]); acc[1][3] = fmaf(a.y, b.w, acc[1][3]);
            acc[2][0] = fmaf(a.z, b.x, acc[2][0]); acc[2][1] = fmaf(a.z, b.y, acc[2][1]);
            acc[2][2] = fmaf(a.z, b.z, acc[2][2]); acc[2][3] = fmaf(a.z, b.w, acc[2][3]);
            acc[3][0] = fmaf(a.w, b.x, acc[3][0]); acc[3][1] = fmaf(a.w, b.y, acc[3][1]);
            acc[3][2] = fmaf(a.w, b.z, acc[3][2]); acc[3][3] = fmaf(a.w, b.w, acc[3][3]);
        }
        if (k0 < K) {
            int nb = buf ^ 1;
            As[nb][ac + 0][ar] = av.x; As[nb][ac + 1][ar] = av.y;
            As[nb][ac + 2][ar] = av.z; As[nb][ac + 3][ar] = av.w;
            *(float4*)&Bs[nb][br][bc] = bv;
        }
        __syncthreads();
        buf ^= 1;
    }
#pragma unroll
    for (int i = 0; i < 4; i++) {
        int r = by * 64 + ty * 4 + i;
        float o[4];
#pragma unroll
        for (int j = 0; j < 4; j++) {
            int cx = bx * 64 + tx * 4 + j;
            float v = acc[i][j];
            if (mode) v = (r == cx ? 2.0f : 0.0f) - v;
            o[j] = v;
        }
        *(float4*)&C[(size_t)r * N + bx * 64 + tx * 4] = make_float4(o[0], o[1], o[2], o[3]);
    }
}

// fbhat = Einv @ v
__global__ void matvec_kernel(const float* __restrict__ Einv, const float* __restrict__ v) {
    int r = blockIdx.x * blockDim.x + threadIdx.x;
    if (r < NXX) {
        float s = 0.f;
        for (int k = 0; k < NXX; k++) s = fmaf(Einv[(size_t)r * NXX + k], v[k], s);
        d_fbhat[r] = s;
    }
}

// ---------------- u projections: out[(t*B + b)*J + j] -------------------------
__global__ void uproj_kernel(const float* __restrict__ u, const float* __restrict__ M,
                             const float* __restrict__ bias, float* __restrict__ out, int J) {
    __shared__ float U_s[NUU][65];
    __shared__ float M_s[64][65];
    int tid = threadIdx.x;
    int j0 = blockIdx.x * 64, t0 = blockIdx.y * 64, b = blockIdx.z;
    for (int i = tid; i < 64 * 64; i += 256) {
        int kk = i >> 6, tt = i & 63;
        U_s[kk][tt] = u[(size_t)b * NUU * TSTEP + (size_t)kk * TSTEP + t0 + tt];
    }
    for (int i = tid; i < 64 * 64; i += 256) {
        int j = i >> 6, k = i & 63;
        M_s[j][k] = M[(size_t)(j0 + j) * NUU + k];
    }
    __syncthreads();
    int lane = tid & 31, wg = tid >> 5;
    float acc0[8] = {}, acc1[8] = {};
    for (int k = 0; k < 64; k++) {
        float u0 = U_s[k][lane], u1 = U_s[k][lane + 32];
#pragma unroll
        for (int j = 0; j < 8; j++) {
            float m = M_s[wg * 8 + j][k];
            acc0[j] = fmaf(u0, m, acc0[j]);
            acc1[j] = fmaf(u1, m, acc1[j]);
        }
    }
    int jj0 = j0 + wg * 8;
    float bsv[8];
#pragma unroll
    for (int j = 0; j < 8; j++) bsv[j] = bias[jj0 + j];
    size_t r0 = ((size_t)(t0 + lane) * BATCH + b) * J + jj0;
    size_t r1 = ((size_t)(t0 + lane + 32) * BATCH + b) * J + jj0;
    *(float4*)&out[r0]     = make_float4(acc0[0] + bsv[0], acc0[1] + bsv[1], acc0[2] + bsv[2], acc0[3] + bsv[3]);
    *(float4*)&out[r0 + 4] = make_float4(acc0[4] + bsv[4], acc0[5] + bsv[5], acc0[6] + bsv[6], acc0[7] + bsv[7]);
    *(float4*)&out[r1]     = make_float4(acc1[0] + bsv[0], acc1[1] + bsv[1], acc1[2] + bsv[2], acc1[3] + bsv[3]);
    *(float4*)&out[r1 + 4] = make_float4(acc1[4] + bsv[4], acc1[5] + bsv[5], acc1[6] + bsv[6], acc1[7] + bsv[7]);
}

// ---------------- init --------------------------------------------------------
__global__ void init_kernel() {
    int i = blockIdx.x * blockDim.x + threadIdx.x;
    int stride = gridDim.x * blockDim.x;
    for (int idx = i; idx < GROUPS * 32; idx += stride) g_cnt[idx] = 0u;
    for (int idx = i; idx < GROUPS * NXX * BGS; idx += stride) d_hbuf[idx] = 0.f;
    for (int idx = i; idx < BATCH * NXX; idx += stride) d_states[idx] = 0.f;  // t=0
}

// ---------------- packed dot: 16 rows x 16 k (interleaved), one batch col -----
// hp = h_s + b (stride 8 per k); wkb = weight base [k][16]; kset: kbase + 4*i
__device__ __forceinline__ void dotp(const float* __restrict__ hp,
                                     const float* __restrict__ wkb,
                                     int kbase, float* __restrict__ acc) {
#pragma unroll
    for (int i = 0; i < 16; i++) {
        int k = kbase + 4 * i;
        float hv = hp[k * BGS];
        const float4* wp = (const float4*)(wkb + k * ROWS);
        float4 w0 = wp[0], w1 = wp[1], w2 = wp[2], w3 = wp[3];
        acc[0]  = fmaf(w0.x, hv, acc[0]);  acc[1]  = fmaf(w0.y, hv, acc[1]);
        acc[2]  = fmaf(w0.z, hv, acc[2]);  acc[3]  = fmaf(w0.w, hv, acc[3]);
        acc[4]  = fmaf(w1.x, hv, acc[4]);  acc[5]  = fmaf(w1.y, hv, acc[5]);
        acc[6]  = fmaf(w1.z, hv, acc[6]);  acc[7]  = fmaf(w1.w, hv, acc[7]);
        acc[8]  = fmaf(w2.x, hv, acc[8]);  acc[9]  = fmaf(w2.y, hv, acc[9]);
        acc[10] = fmaf(w2.z, hv, acc[10]); acc[11] = fmaf(w2.w, hv, acc[11]);
        acc[12] = fmaf(w3.x, hv, acc[12]); acc[13] = fmaf(w3.y, hv, acc[13]);
        acc[14] = fmaf(w3.z, hv, acc[14]); acc[15] = fmaf(w3.w, hv, acc[15]);
    }
}

// ---------------- persistent sequential recurrence ----------------------------
// 4 groups x 32 CTAs; group g: batches [8g, 8g+8); CTA: 16 rows.
__global__ void __launch_bounds__(RTHR, 1) recur_kernel() {
    extern __shared__ float sm[];
    float* wC  = sm;                 // [512][16]
    float* wA  = wC + 8192;
    float* wB  = wA + 8192;
    float* h_s = wB + 8192;          // [512][8]
    float* w_s = h_s + NXX * BGS;    // [512][8]
    float* pW  = w_s + NWW * BGS;    // [32][PST]
    float* pA  = pW + 32 * PST;
    float* pB  = pA + 32 * PST;

    int tid  = threadIdx.x;
    int cta  = blockIdx.x;
    int g    = cta >> 5;
    int j0   = (cta & 31) * ROWS;
    int warp = tid >> 5, lane = tid & 31;
    int kh = lane >> 3, b = lane & 7;
    int rrow = tid >> 3, rb = tid & 7;         // reduce mapping (tid<128)
    int roff = rrow * BGS + rb;
    int bb = g * BGS + rb;

    float* hg = d_hbuf + g * NXX * BGS;
    float* wg = d_wvec + g * NWW * BGS;
    unsigned* cnt = &g_cnt[g * 32];

    // stage weight slices [k][row] (resident for whole kernel)
    for (int i = tid; i < 8192; i += RTHR) {
        int k = i >> 4, c = i & 15;
        wC[i] = d_Cv[(size_t)(j0 + c) * NXX + k];
        wA[i] = d_Ahat[(size_t)(j0 + c) * NXX + k];
        wB[i] = d_Bhat[(size_t)(j0 + c) * NWW + k];
    }
    __syncthreads();

    int kbase = warp * 64 + kh;
    float* ppW = pW + (warp * 4 + kh) * PST + b;
    float* ppA = pA + (warp * 4 + kh) * PST + b;
    float* ppB = pB + (warp * 4 + kh) * PST + b;

    for (int t = 0; t < TSTEP; t++) {
        // prefetch G terms (in flight during spin)
        float g1 = 0.f, g2 = 0.f;
        if (tid < 128) {
            g1 = d_G1[((size_t)t * BATCH + bb) * NWW + j0 + rrow];
            if (t < TSTEP - 1)
                g2 = d_G2[((size_t)t * BATCH + bb) * NXX + j0 + rrow];
        }
        // wait h(t)
        if (t > 0) {
            if (lane == 0) wait_cnt(cnt, 256u * (unsigned)t);
            __syncwarp();
        }
        // per-warp copy of own 64-k chunk of h (512 floats = 128 float4)
        {
            const float4* src = (const float4*)hg + warp * 128;
            float4* dst = (float4*)h_s + warp * 128;
#pragma unroll
            for (int i = 0; i < 4; i++) dst[lane + 32 * i] = ldcg4(&src[lane + 32 * i]);
        }
        __syncwarp();
        // phase A: Cv @ h
        {
            float acc[16] = {};
            dotp(h_s + b, wC, kbase, acc);
#pragma unroll
            for (int r = 0; r < 16; r++) ppW[r * 8] = acc[r];
        }
        __syncthreads();  // #1: pW complete
        if (tid < 128) {
            float v = g1;
#pragma unroll
            for (int p = 0; p < 32; p++) v += pW[p * PST + roff];
            v = fmaxf(v, 0.f);
            wg[(j0 + rrow) * BGS + rb] = v;
            d_Wb[((size_t)t * BATCH + bb) * NWW + j0 + rrow] = v;
            __syncwarp();
            if (lane == 0) bar_arrive(cnt);   // w(t) ready (4 arrives/CTA)
        }
        if (t == TSTEP - 1) break;
        // Ahat @ h (hides the w barrier)
        {
            float acc[16] = {};
            dotp(h_s + b, wA, kbase, acc);
#pragma unroll
            for (int r = 0; r < 16; r++) ppA[r * 8] = acc[r];
        }
        // wait w(t)
        if (lane == 0) wait_cnt(cnt, 256u * (unsigned)t + 128u);
        __syncwarp();
        {
            const float4* src = (const float4*)wg + warp * 128;
            float4* dst = (float4*)w_s + warp * 128;
#pragma unroll
            for (int i = 0; i < 4; i++) dst[lane + 32 * i] = ldcg4(&src[lane + 32 * i]);
        }
        __syncwarp();
        // Bhat @ w
        {
            float acc[16] = {};
            dotp(w_s + b, wB, kbase, acc);
#pragma unroll
            for (int r = 0; r < 16; r++) ppB[r * 8] = acc[r];
        }
        __syncthreads();  // #2: pA, pB complete
        if (tid < 128) {
            float v = g2;
#pragma unroll
            for (int p = 0; p < 32; p++)
                v += pA[p * PST + roff] + pB[p * PST + roff];
            hg[(j0 + rrow) * BGS + rb] = v;
            d_states[((size_t)(t + 1) * BATCH + bb) * NXX + j0 + rrow] = v;
            __syncwarp();
            if (lane == 0) bar_arrive(cnt);   // h(t+1) ready
        }
    }
}

// ---------------- epilogue: y = states@C1.T + W@D11.T + u@D12.T + by ----------
__global__ void yfinal_kernel(const float* __restrict__ u, const float* __restrict__ C1,
                              const float* __restrict__ D11, const float* __restrict__ D12,
                              const float* __restrict__ by, float* __restrict__ out) {
    __shared__ float As[64][65];
    __shared__ float Bs[64][68];
    int tid = threadIdx.x;
    int tx = tid & 15, ty = tid >> 4;
    int t0 = blockIdx.x * 64, b = blockIdx.y;
    float acc[4][4] = {};
    for (int seg = 0; seg < 3; seg++) {
        int nchunk = (seg == 2) ? 1 : 8;
        const float* Am = (seg == 0) ? C1 : (seg == 1) ? D11 : D12;
        int Ksz = (seg == 2) ? 64 : 512;
        for (int ch = 0; ch < nchunk; ch++) {
            int x0 = ch * 64;
            for (int i = tid; i < 64 * 64; i += 256) {
                int j = i >> 6, k = i & 63;
                As[j][k] = Am[(size_t)j * Ksz + x0 + k];
            }
            if (seg == 2) {
                for (int i = tid; i < 64 * 64; i += 256) {
                    int k = i >> 6, tt = i & 63;
                    Bs[k][tt] = u[((size_t)b * NUU + k) * TSTEP + t0 + tt];
                }
            } else {
                const float* S = (seg == 0) ? d_states : d_Wb;
                for (int i = tid; i < 64 * 64; i += 256) {
                    int tt = i >> 6, xx = i & 63;
                    Bs[xx][tt] = S[((size_t)(t0 + tt) * BATCH + b) * 512 + x0 + xx];
                }
            }
            __syncthreads();
#pragma unroll 8
            for (int k = 0; k < 64; k++) {
                float a0 = As[ty * 4 + 0][k];
                float a1 = As[ty * 4 + 1][k];
                float a2 = As[ty * 4 + 2][k];
                float a3 = As[ty * 4 + 3][k];
                float4 bv = *(const float4*)&Bs[k][tx * 4];
                acc[0][0] = fmaf(a0, bv.x, acc[0][0]); acc[0][1] = fmaf(a0, bv.y, acc[0][1]);
                acc[0][2] = fmaf(a0, bv.z, acc[0][2]); acc[0][3] = fmaf(a0, bv.w, acc[0][3]);
                acc[1][0] = fmaf(a1, bv.x, acc[1][0]); acc[1][1] = fmaf(a1, bv.y, acc[1][1]);
                acc[1][2] = fmaf(a1, bv.z, acc[1][2]); acc[1][3] = fmaf(a1, bv.w, acc[1][3]);
                acc[2][0] = fmaf(a2, bv.x, acc[2][0]); acc[2][1] = fmaf(a2, bv.y, acc[2][1]);
                acc[2][2] = fmaf(a2, bv.z, acc[2][2]); acc[2][3] = fmaf(a2, bv.w, acc[2][3]);
                acc[3][0] = fmaf(a3, bv.x, acc[3][0]); acc[3][1] = fmaf(a3, bv.y, acc[3][1]);
                acc[3][2] = fmaf(a3, bv.z, acc[3][2]); acc[3][3] = fmaf(a3, bv.w, acc[3][3]);
            }
            __syncthreads();
        }
    }
#pragma unroll
    for (int i = 0; i < 4; i++) {
        int j = ty * 4 + i;
        float bj = by[j];
        float4 o = make_float4(acc[i][0] + bj, acc[i][1] + bj, acc[i][2] + bj, acc[i][3] + bj);
        *(float4*)&out[((size_t)b * NYY + j) * TSTEP + t0 + tx * 4] = o;
    }
}

// ---------------- launch ------------------------------------------------------
extern "C" void kernel_launch(void* const* d_in, const int* in_sizes, int n_in,
                              void* d_out, int out_size) {
    const float* u      = (const float*)d_in[0];
    const float* E      = (const float*)d_in[1];
    const float* F_w    = (const float*)d_in[2];
    const float* F_b    = (const float*)d_in[3];
    const float* B1_w   = (const float*)d_in[4];
    const float* B2_w   = (const float*)d_in[5];
    const float* C2tild = (const float*)d_in[6];
    const float* bv     = (const float*)d_in[7];
    const float* Dtild  = (const float*)d_in[8];
    const float* C1_w   = (const float*)d_in[9];
    const float* D11_w  = (const float*)d_in[10];
    const float* D12_w  = (const float*)d_in[11];
    const float* by     = (const float*)d_in[12];
    const float* multis = (const float*)d_in[13];
    float* out = (float*)d_out;

    float *X, *X2, *T1, *Ahat, *Bhat, *B2hat, *Dv, *G1, *G2, *fbhat;
    cudaGetSymbolAddress((void**)&X,     d_X);
    cudaGetSymbolAddress((void**)&X2,    d_X2);
    cudaGetSymbolAddress((void**)&T1,    d_T1);
    cudaGetSymbolAddress((void**)&Ahat,  d_Ahat);
    cudaGetSymbolAddress((void**)&Bhat,  d_Bhat);
    cudaGetSymbolAddress((void**)&B2hat, d_B2hat);
    cudaGetSymbolAddress((void**)&Dv,    d_Dv);
    cudaGetSymbolAddress((void**)&G1,    d_G1);
    cudaGetSymbolAddress((void**)&G2,    d_G2);
    cudaGetSymbolAddress((void**)&fbhat, d_fbhat);

    // 3*8192 + 2*4096 + 3*32*PST floats
    const int SMEM_RECUR = (3 * 8192 + 2 * 4096 + 3 * 32 * PST) * 4;
    cudaFuncSetAttribute(recur_kernel, cudaFuncAttributeMaxDynamicSharedMemorySize, SMEM_RECUR);

    prep_kernel<<<256, 256>>>(C2tild, multis, Dtild, E);

    // Newton-Schulz: X <- X(2I - E X), 3 iterations (residual ~2.6e-6)
    dim3 g88(8, 8);
    for (int it = 0; it < 3; it++) {
        gemm_rrr<<<g88, 256>>>(E, X, T1, 512, 512, 512, 1);   // T1 = 2I - E@X
        gemm_rrr<<<g88, 256>>>(X, T1, X2, 512, 512, 512, 0);
        float* tmp = X; X = X2; X2 = tmp;
    }

    gemm_rrr<<<g88, 256>>>(X, F_w, Ahat, 512, 512, 512, 0);
    gemm_rrr<<<g88, 256>>>(X, B1_w, Bhat, 512, 512, 512, 0);
    gemm_rrr<<<dim3(1, 8), 256>>>(X, B2_w, B2hat, 512, 64, 512, 0);
    matvec_kernel<<<2, 256>>>(X, F_b);

    uproj_kernel<<<dim3(8, 16, 32), 256>>>(u, Dv, bv, G1, NWW);
    uproj_kernel<<<dim3(8, 16, 32), 256>>>(u, B2hat, fbhat, G2, NXX);

    init_kernel<<<64, 256>>>();
    recur_kernel<<<RCTAS, RTHR, SMEM_RECUR>>>();

    yfinal_kernel<<<dim3(16, 32), 256>>>(u, C1_w, D11_w, D12_w, by, out);
}

// round 6
// speedup vs baseline: 2.1379x; 1.0149x over previous
#include <cuda_runtime.h>
#include <cstddef>

#define BATCH 32
#define NUU   64
#define NYY   64
#define NXX   512
#define NWW   512
#define TSTEP 1024
#define RCTAS 128
#define RTHR  256
#define GROUPS 4
#define GCTAS 32     // CTAs per group
#define BGS   8      // batches per group
#define ROWS  16     // rows per CTA
#define PST   136    // partial-buffer stride (floats)

// ---------------- device scratch (__device__ globals: allocation-free) --------
__device__ float d_Cv[NWW * NXX];
__device__ float d_Dv[NWW * NUU];
__device__ float d_X[NXX * NXX];
__device__ float d_X2[NXX * NXX];
__device__ float d_T1[NXX * NXX];
__device__ float d_Ahat[NXX * NXX];
__device__ float d_Bhat[NXX * NWW];
__device__ float d_B2hat[NXX * NUU];
__device__ float d_fbhat[NXX];
__device__ float d_G1[(size_t)TSTEP * BATCH * NWW];     // [t][b][j]
__device__ float d_G2[(size_t)TSTEP * BATCH * NXX];     // [t][b][x]
__device__ float d_states[(size_t)TSTEP * BATCH * NXX]; // [t][b][x]
__device__ float d_Wb[(size_t)TSTEP * BATCH * NWW];     // [t][b][j]
__device__ float d_hbuf[2 * GROUPS * NXX * BGS];  // [parity][g][x][b8]
__device__ float d_wvec[GROUPS * NWW * BGS];      // [g][j][b8]
__device__ unsigned g_cw[GROUPS * 8 * 32];        // per-group per-octile w flags (128B pad)
__device__ unsigned g_ch[GROUPS * 8 * 32];        // per-group per-octile h flags
__device__ unsigned g_pcnt;                       // prep-gemm grid barrier

// ---------------- sync primitives ---------------------------------------------
__device__ __forceinline__ void rel_add1(unsigned* cnt) {
    asm volatile("red.release.gpu.add.u32 [%0], 1;" :: "l"(cnt) : "memory");
}
__device__ __forceinline__ void wait_cnt(unsigned* cnt, unsigned target) {
    unsigned v;
    do {
        asm volatile("ld.acquire.gpu.u32 %0, [%1];" : "=r"(v) : "l"(cnt) : "memory");
    } while (v < target);
}
__device__ __forceinline__ float4 ldcg4(const float4* p) {
    float4 v;
    asm volatile("ld.global.cg.v4.f32 {%0,%1,%2,%3}, [%4];"
                 : "=f"(v.x), "=f"(v.y), "=f"(v.z), "=f"(v.w) : "l"(p));
    return v;
}

// ---------------- prep: Cv, Dv, X0 = 2I - E, reset prep barrier ---------------
__global__ void prep_kernel(const float* __restrict__ C2, const float* __restrict__ mult,
                            const float* __restrict__ Dt, const float* __restrict__ E) {
    int i = blockIdx.x * blockDim.x + threadIdx.x;
    int stride = gridDim.x * blockDim.x;
    if (i == 0) g_pcnt = 0u;
    for (int idx = i; idx < NWW * NXX; idx += stride) {
        int r = idx / NXX;
        d_Cv[idx] = C2[idx] / mult[r];
    }
    for (int idx = i; idx < NWW * NUU; idx += stride) {
        int r = idx / NUU;
        d_Dv[idx] = Dt[idx] / mult[r];
    }
    for (int idx = i; idx < NXX * NXX; idx += stride) {
        int r = idx / NXX, c = idx % NXX;
        d_X[idx] = (r == c ? 2.0f : 0.0f) - E[idx];
    }
}

// ---------------- fused prep GEMM chain (persistent, 64 CTAs) -----------------
__device__ __forceinline__ void gemm_tile(const float* __restrict__ A, const float* __restrict__ Bm,
                                          float* __restrict__ C, int N, int K, int mode,
                                          int bx, int by,
                                          float (*As)[16][64], float (*Bs)[16][64]) {
    int tid = threadIdx.x;
    int tx = tid & 15, ty = tid >> 4;
    int ar = tid >> 2, ac = (tid & 3) << 2;
    int br = tid >> 4, bc = (tid & 15) << 2;
    const float* Aptr = A + (size_t)(by * 64 + ar) * K + ac;
    const float* Bptr = Bm + (size_t)br * N + bx * 64 + bc;

    float4 av = *(const float4*)Aptr;
    float4 bv = *(const float4*)Bptr;
    As[0][ac + 0][ar] = av.x; As[0][ac + 1][ar] = av.y;
    As[0][ac + 2][ar] = av.z; As[0][ac + 3][ar] = av.w;
    *(float4*)&Bs[0][br][bc] = bv;
    __syncthreads();

    float acc[4][4] = {};
    int buf = 0;
    for (int k0 = 16; k0 <= K; k0 += 16) {
        if (k0 < K) {
            av = *(const float4*)(Aptr + k0);
            bv = *(const float4*)(Bptr + (size_t)k0 * N);
        }
#pragma unroll
        for (int k = 0; k < 16; k++) {
            float4 a = *(const float4*)&As[buf][k][ty * 4];
            float4 b = *(const float4*)&Bs[buf][k][tx * 4];
            acc[0][0] = fmaf(a.x, b.x, acc[0][0]); acc[0][1] = fmaf(a.x, b.y, acc[0][1]);
            acc[0][2] = fmaf(a.x, b.z, acc[0][2]); acc[0][3] = fmaf(a.x, b.w, acc[0][3]);
            acc[1][0] = fmaf(a.y, b.x, acc[1][0]); acc[1][1] = fmaf(a.y, b.y, acc[1][1]);
            acc[1][2] = fmaf(a.y, b.z, acc[1][2]); acc[1][3] = fmaf(a.y, b.w, acc[1][3]);
            acc[2][0] = fmaf(a.z, b.x, acc[2][0]); acc[2][1] = fmaf(a.z, b.y, acc[2][1]);
            acc[2][2] = fmaf(a.z, b.z, acc[2][2]); acc[2][3] = fmaf(a.z, b.w, acc[2][3]);
            acc[3][0] = fmaf(a.w, b.x, acc[3][0]); acc[3][1] = fmaf(a.w, b.y, acc[3][1]);
            acc[3][2] = fmaf(a.w, b.z, acc[3][2]); acc[3][3] = fmaf(a.w, b.w, acc[3][3]);
        }
        if (k0 < K) {
            int nb = buf ^ 1;
            As[nb][ac + 0][ar] = av.x; As[nb][ac + 1][ar] = av.y;
            As[nb][ac + 2][ar] = av.z; As[nb][ac + 3][ar] = av.w;
            *(float4*)&Bs[nb][br][bc] = bv;
        }
        __syncthreads();
        buf ^= 1;
    }
#pragma unroll
    for (int i = 0; i < 4; i++) {
        int r = by * 64 + ty * 4 + i;
        float o[4];
#pragma unroll
        for (int j = 0; j < 4; j++) {
            int cx = bx * 64 + tx * 4 + j;
            float v = acc[i][j];
            if (mode) v = (r == cx ? 2.0f : 0.0f) - v;
            o[j] = v;
        }
        *(float4*)&C[(size_t)r * N + bx * 64 + tx * 4] = make_float4(o[0], o[1], o[2], o[3]);
    }
}

__device__ __forceinline__ void gbar(unsigned gen) {
    __threadfence();
    __syncthreads();
    if (threadIdx.x == 0) {
        rel_add1(&g_pcnt);
        wait_cnt(&g_pcnt, 64u * gen);
    }
    __syncthreads();
}

__global__ void __launch_bounds__(256, 1) prepgemm_kernel(
        const float* __restrict__ E, const float* __restrict__ F_w,
        const float* __restrict__ F_b, const float* __restrict__ B1_w,
        const float* __restrict__ B2_w) {
    __shared__ float As[2][16][64];
    __shared__ float Bs[2][16][64];
    int cta = blockIdx.x;
    int bx = cta & 7, by = cta >> 3;

    // Newton-Schulz: 3 iterations, X0 in d_X
    gemm_tile(E, d_X, d_T1, 512, 512, 1, bx, by, As, Bs);  gbar(1);
    gemm_tile(d_X, d_T1, d_X2, 512, 512, 0, bx, by, As, Bs); gbar(2);
    gemm_tile(E, d_X2, d_T1, 512, 512, 1, bx, by, As, Bs); gbar(3);
    gemm_tile(d_X2, d_T1, d_X, 512, 512, 0, bx, by, As, Bs); gbar(4);
    gemm_tile(E, d_X, d_T1, 512, 512, 1, bx, by, As, Bs);  gbar(5);
    gemm_tile(d_X, d_T1, d_X2, 512, 512, 0, bx, by, As, Bs); gbar(6);
    // d_X2 = Einv
    gemm_tile(d_X2, F_w, d_Ahat, 512, 512, 0, bx, by, As, Bs);
    gemm_tile(d_X2, B1_w, d_Bhat, 512, 512, 0, bx, by, As, Bs);
    if (cta < 8) {
        gemm_tile(d_X2, B2_w, d_B2hat, 64, 512, 0, 0, cta, As, Bs);
    } else if (cta < 16 && threadIdx.x < 64) {
        int r = (cta - 8) * 64 + threadIdx.x;
        float s = 0.f;
        for (int k = 0; k < NXX; k++) s = fmaf(d_X2[(size_t)r * NXX + k], F_b[k], s);
        d_fbhat[r] = s;
    }
}

// ---------------- u projections: out[(t*B + b)*J + j] -------------------------
__global__ void uproj_kernel(const float* __restrict__ u, const float* __restrict__ M,
                             const float* __restrict__ bias, float* __restrict__ out, int J) {
    __shared__ float U_s[NUU][65];
    __shared__ float M_s[64][65];
    int tid = threadIdx.x;
    int j0 = blockIdx.x * 64, t0 = blockIdx.y * 64, b = blockIdx.z;
    for (int i = tid; i < 64 * 64; i += 256) {
        int kk = i >> 6, tt = i & 63;
        U_s[kk][tt] = u[(size_t)b * NUU * TSTEP + (size_t)kk * TSTEP + t0 + tt];
    }
    for (int i = tid; i < 64 * 64; i += 256) {
        int j = i >> 6, k = i & 63;
        M_s[j][k] = M[(size_t)(j0 + j) * NUU + k];
    }
    __syncthreads();
    int lane = tid & 31, wg = tid >> 5;
    float acc0[8] = {}, acc1[8] = {};
    for (int k = 0; k < 64; k++) {
        float u0 = U_s[k][lane], u1 = U_s[k][lane + 32];
#pragma unroll
        for (int j = 0; j < 8; j++) {
            float m = M_s[wg * 8 + j][k];
            acc0[j] = fmaf(u0, m, acc0[j]);
            acc1[j] = fmaf(u1, m, acc1[j]);
        }
    }
    int jj0 = j0 + wg * 8;
    float bsv[8];
#pragma unroll
    for (int j = 0; j < 8; j++) bsv[j] = bias[jj0 + j];
    size_t r0 = ((size_t)(t0 + lane) * BATCH + b) * J + jj0;
    size_t r1 = ((size_t)(t0 + lane + 32) * BATCH + b) * J + jj0;
    *(float4*)&out[r0]     = make_float4(acc0[0] + bsv[0], acc0[1] + bsv[1], acc0[2] + bsv[2], acc0[3] + bsv[3]);
    *(float4*)&out[r0 + 4] = make_float4(acc0[4] + bsv[4], acc0[5] + bsv[5], acc0[6] + bsv[6], acc0[7] + bsv[7]);
    *(float4*)&out[r1]     = make_float4(acc1[0] + bsv[0], acc1[1] + bsv[1], acc1[2] + bsv[2], acc1[3] + bsv[3]);
    *(float4*)&out[r1 + 4] = make_float4(acc1[4] + bsv[4], acc1[5] + bsv[5], acc1[6] + bsv[6], acc1[7] + bsv[7]);
}

// ---------------- init --------------------------------------------------------
__global__ void init_kernel() {
    int i = blockIdx.x * blockDim.x + threadIdx.x;
    int stride = gridDim.x * blockDim.x;
    for (int idx = i; idx < GROUPS * 8 * 32; idx += stride) {
        g_cw[idx] = 0u;
        g_ch[idx] = 0u;
    }
    for (int idx = i; idx < 2 * GROUPS * NXX * BGS; idx += stride) d_hbuf[idx] = 0.f;
    for (int idx = i; idx < BATCH * NXX; idx += stride) d_states[idx] = 0.f;  // t=0
}

// ---------------- dot: 16 rows x 16 k (interleaved), one batch col ------------
__device__ __forceinline__ void dotp(const float* __restrict__ hp,
                                     const float* __restrict__ wkb,
                                     int kbase, float* __restrict__ acc) {
#pragma unroll
    for (int i = 0; i < 16; i++) {
        int k = kbase + 4 * i;
        float hv = hp[k * BGS];
        const float4* wp = (const float4*)(wkb + k * ROWS);
        float4 w0 = wp[0], w1 = wp[1], w2 = wp[2], w3 = wp[3];
        acc[0]  = fmaf(w0.x, hv, acc[0]);  acc[1]  = fmaf(w0.y, hv, acc[1]);
        acc[2]  = fmaf(w0.z, hv, acc[2]);  acc[3]  = fmaf(w0.w, hv, acc[3]);
        acc[4]  = fmaf(w1.x, hv, acc[4]);  acc[5]  = fmaf(w1.y, hv, acc[5]);
        acc[6]  = fmaf(w1.z, hv, acc[6]);  acc[7]  = fmaf(w1.w, hv, acc[7]);
        acc[8]  = fmaf(w2.x, hv, acc[8]);  acc[9]  = fmaf(w2.y, hv, acc[9]);
        acc[10] = fmaf(w2.z, hv, acc[10]); acc[11] = fmaf(w2.w, hv, acc[11]);
        acc[12] = fmaf(w3.x, hv, acc[12]); acc[13] = fmaf(w3.y, hv, acc[13]);
        acc[14] = fmaf(w3.z, hv, acc[14]); acc[15] = fmaf(w3.w, hv, acc[15]);
    }
}

// ---------------- persistent sequential recurrence (dataflow flags) -----------
// 4 groups x 32 CTAs; group g: batches [8g, 8g+8); CTA: 16 rows.
// Per-octile flags: consumer warp w depends only on CTAs [4w, 4w+4) of its group.
__global__ void __launch_bounds__(RTHR, 1) recur_kernel() {
    extern __shared__ float sm[];
    float* wC  = sm;                 // [512][16]
    float* wA  = wC + 8192;
    float* wB  = wA + 8192;
    float* h_s = wB + 8192;          // [512][8]
    float* w_s = h_s + NXX * BGS;    // [512][8]
    float* pW  = w_s + NWW * BGS;    // [32][PST]  outputs at b*16+row
    float* pA  = pW + 32 * PST;
    float* pB  = pA + 32 * PST;

    int tid  = threadIdx.x;
    int cta  = blockIdx.x;
    int g    = cta >> 5;
    int lc   = cta & 31;
    int j0   = lc * ROWS;
    int warp = tid >> 5, lane = tid & 31;
    int kh = lane >> 3, b = lane & 7;
    int rrow = tid & 15, rb = tid >> 4;        // reduce mapping (tid<128): coalesced rows
    int bb = g * BGS + rb;

    unsigned* cw_arr = &g_cw[(g * 8 + (lc >> 2)) * 32];   // my arrive flag (w)
    unsigned* ch_arr = &g_ch[(g * 8 + (lc >> 2)) * 32];   // my arrive flag (h)
    unsigned* cw_poll = &g_cw[(g * 8 + warp) * 32];       // my warp's dependency (w)
    unsigned* ch_poll = &g_ch[(g * 8 + warp) * 32];       // my warp's dependency (h)

    float* wg = d_wvec + g * NWW * BGS;

    // stage weight slices [k][row] (resident for whole kernel)
    for (int i = tid; i < 8192; i += RTHR) {
        int k = i >> 4, c = i & 15;
        wC[i] = d_Cv[(size_t)(j0 + c) * NXX + k];
        wA[i] = d_Ahat[(size_t)(j0 + c) * NXX + k];
        wB[i] = d_Bhat[(size_t)(j0 + c) * NWW + k];
    }
    __syncthreads();

    int kbase = warp * 64 + kh;
    int slot = warp * 4 + kh;
    float* ppW = pW + slot * PST + b * 16;
    float* ppA = pA + slot * PST + b * 16;
    float* ppB = pB + slot * PST + b * 16;
    int roff = rb * 16 + rrow;   // partial-buffer output index (== tid for tid<128)

    for (int t = 0; t < TSTEP; t++) {
        // prefetch G terms (in flight during poll)
        float g1 = 0.f, g2 = 0.f;
        if (tid < 128) {
            g1 = __ldcg(&d_G1[((size_t)t * BATCH + bb) * NWW + j0 + rrow]);
            if (t < TSTEP - 1)
                g2 = __ldcg(&d_G2[((size_t)t * BATCH + bb) * NXX + j0 + rrow]);
        }
        // wait for this warp's h(t) octile, copy it
        if (t > 0) {
            if (lane == 0) wait_cnt(ch_poll, 512u * (unsigned)t);
            __syncwarp();
        }
        {
            const float4* src = (const float4*)(d_hbuf +
                ((size_t)(t & 1) * GROUPS + g) * (NXX * BGS)) + warp * 128;
            float4* dst = (float4*)h_s + warp * 128;
#pragma unroll
            for (int i = 0; i < 4; i++) dst[lane + 32 * i] = ldcg4(&src[lane + 32 * i]);
        }
        __syncwarp();
        // phase A: Cv @ h
        {
            float acc[16] = {};
            dotp(h_s + b, wC, kbase, acc);
#pragma unroll
            for (int r = 0; r < 16; r++) ppW[r] = acc[r];
        }
        __syncthreads();  // #1: pW complete
        if (tid < 128) {
            float v = g1;
#pragma unroll
            for (int p = 0; p < 32; p++) v += pW[p * PST + roff];
            v = fmaxf(v, 0.f);
            wg[(j0 + rrow) * BGS + rb] = v;
            d_Wb[((size_t)t * BATCH + bb) * NWW + j0 + rrow] = v;
            rel_add1(cw_arr);   // this thread's own w store is release-ordered
        }
        if (t == TSTEP - 1) break;
        // Ahat @ h (independent of w — overlaps other CTAs' phase A)
        {
            float acc[16] = {};
            dotp(h_s + b, wA, kbase, acc);
#pragma unroll
            for (int r = 0; r < 16; r++) ppA[r] = acc[r];
        }
        // wait for this warp's w(t) octile, copy it
        if (lane == 0) wait_cnt(cw_poll, 512u * (unsigned)(t + 1));
        __syncwarp();
        {
            const float4* src = (const float4*)wg + warp * 128;
            float4* dst = (float4*)w_s + warp * 128;
#pragma unroll
            for (int i = 0; i < 4; i++) dst[lane + 32 * i] = ldcg4(&src[lane + 32 * i]);
        }
        __syncwarp();
        // Bhat @ w
        {
            float acc[16] = {};
            dotp(w_s + b, wB, kbase, acc);
#pragma unroll
            for (int r = 0; r < 16; r++) ppB[r] = acc[r];
        }
        __syncthreads();  // #2: pA, pB complete
        if (tid < 128) {
            float v = g2;
#pragma unroll
            for (int p = 0; p < 32; p++)
                v += pA[p * PST + roff] + pB[p * PST + roff];
            d_hbuf[((size_t)((t + 1) & 1) * GROUPS + g) * (NXX * BGS) + (j0 + rrow) * BGS + rb] = v;
            d_states[((size_t)(t + 1) * BATCH + bb) * NXX + j0 + rrow] = v;
            rel_add1(ch_arr);
        }
    }
}

// ---------------- epilogue: y = states@C1.T + W@D11.T + u@D12.T + by ----------
__global__ void yfinal_kernel(const float* __restrict__ u, const float* __restrict__ C1,
                              const float* __restrict__ D11, const float* __restrict__ D12,
                              const float* __restrict__ by, float* __restrict__ out) {
    __shared__ float As[64][65];
    __shared__ float Bs[64][68];
    int tid = threadIdx.x;
    int tx = tid & 15, ty = tid >> 4;
    int t0 = blockIdx.x * 64, b = blockIdx.y;
    float acc[4][4] = {};
    for (int seg = 0; seg < 3; seg++) {
        int nchunk = (seg == 2) ? 1 : 8;
        const float* Am = (seg == 0) ? C1 : (seg == 1) ? D11 : D12;
        int Ksz = (seg == 2) ? 64 : 512;
        for (int ch = 0; ch < nchunk; ch++) {
            int x0 = ch * 64;
            for (int i = tid; i < 64 * 64; i += 256) {
                int j = i >> 6, k = i & 63;
                As[j][k] = Am[(size_t)j * Ksz + x0 + k];
            }
            if (seg == 2) {
                for (int i = tid; i < 64 * 64; i += 256) {
                    int k = i >> 6, tt = i & 63;
                    Bs[k][tt] = u[((size_t)b * NUU + k) * TSTEP + t0 + tt];
                }
            } else {
                const float* S = (seg == 0) ? d_states : d_Wb;
                for (int i = tid; i < 64 * 64; i += 256) {
                    int tt = i >> 6, xx = i & 63;
                    Bs[xx][tt] = S[((size_t)(t0 + tt) * BATCH + b) * 512 + x0 + xx];
                }
            }
            __syncthreads();
#pragma unroll 8
            for (int k = 0; k < 64; k++) {
                float a0 = As[ty * 4 + 0][k];
                float a1 = As[ty * 4 + 1][k];
                float a2 = As[ty * 4 + 2][k];
                float a3 = As[ty * 4 + 3][k];
                float4 bv = *(const float4*)&Bs[k][tx * 4];
                acc[0][0] = fmaf(a0, bv.x, acc[0][0]); acc[0][1] = fmaf(a0, bv.y, acc[0][1]);
                acc[0][2] = fmaf(a0, bv.z, acc[0][2]); acc[0][3] = fmaf(a0, bv.w, acc[0][3]);
                acc[1][0] = fmaf(a1, bv.x, acc[1][0]); acc[1][1] = fmaf(a1, bv.y, acc[1][1]);
                acc[1][2] = fmaf(a1, bv.z, acc[1][2]); acc[1][3] = fmaf(a1, bv.w, acc[1][3]);
                acc[2][0] = fmaf(a2, bv.x, acc[2][0]); acc[2][1] = fmaf(a2, bv.y, acc[2][1]);
                acc[2][2] = fmaf(a2, bv.z, acc[2][2]); acc[2][3] = fmaf(a2, bv.w, acc[2][3]);
                acc[3][0] = fmaf(a3, bv.x, acc[3][0]); acc[3][1] = fmaf(a3, bv.y, acc[3][1]);
                acc[3][2] = fmaf(a3, bv.z, acc[3][2]); acc[3][3] = fmaf(a3, bv.w, acc[3][3]);
            }
            __syncthreads();
        }
    }
#pragma unroll
    for (int i = 0; i < 4; i++) {
        int j = ty * 4 + i;
        float bj = by[j];
        float4 o = make_float4(acc[i][0] + bj, acc[i][1] + bj, acc[i][2] + bj, acc[i][3] + bj);
        *(float4*)&out[((size_t)b * NYY + j) * TSTEP + t0 + tx * 4] = o;
    }
}

// ---------------- launch ------------------------------------------------------
extern "C" void kernel_launch(void* const* d_in, const int* in_sizes, int n_in,
                              void* d_out, int out_size) {
    const float* u      = (const float*)d_in[0];
    const float* E      = (const float*)d_in[1];
    const float* F_w    = (const float*)d_in[2];
    const float* F_b    = (const float*)d_in[3];
    const float* B1_w   = (const float*)d_in[4];
    const float* B2_w   = (const float*)d_in[5];
    const float* C2tild = (const float*)d_in[6];
    const float* bv     = (const float*)d_in[7];
    const float* Dtild  = (const float*)d_in[8];
    const float* C1_w   = (const float*)d_in[9];
    const float* D11_w  = (const float*)d_in[10];
    const float* D12_w  = (const float*)d_in[11];
    const float* by     = (const float*)d_in[12];
    const float* multis = (const float*)d_in[13];
    float* out = (float*)d_out;

    float *Dv, *G1, *G2, *B2hat, *fbhat;
    cudaGetSymbolAddress((void**)&Dv,    d_Dv);
    cudaGetSymbolAddress((void**)&G1,    d_G1);
    cudaGetSymbolAddress((void**)&G2,    d_G2);
    cudaGetSymbolAddress((void**)&B2hat, d_B2hat);
    cudaGetSymbolAddress((void**)&fbhat, d_fbhat);

    const int SMEM_RECUR = (3 * 8192 + 2 * 4096 + 3 * 32 * PST) * 4;
    cudaFuncSetAttribute(recur_kernel, cudaFuncAttributeMaxDynamicSharedMemorySize, SMEM_RECUR);

    // 1) Cv, Dv, X0 = 2I - E, reset prep barrier
    prep_kernel<<<256, 256>>>(C2tild, multis, Dtild, E);
    // 2) fused Newton-Schulz (3 iters) + weight folding
    prepgemm_kernel<<<64, 256>>>(E, F_w, F_b, B1_w, B2_w);
    // 3,4) input-driven terms
    uproj_kernel<<<dim3(8, 16, 32), 256>>>(u, Dv, bv, G1, NWW);
    uproj_kernel<<<dim3(8, 16, 32), 256>>>(u, B2hat, fbhat, G2, NXX);
    // 5) init flags + state
    init_kernel<<<64, 256>>>();
    // 6) sequential recurrence  (ncu -s 5 -c 1 profiles THIS kernel)
    recur_kernel<<<RCTAS, RTHR, SMEM_RECUR>>>();
    // 7) epilogue
    yfinal_kernel<<<dim3(16, 32), 256>>>(u, C1_w, D11_w, D12_w, by, out);
}

// round 8
// speedup vs baseline: 2.2008x; 1.0294x over previous
#include <cuda_runtime.h>
#include <cstddef>

#define BATCH 32
#define NUU   64
#define NYY   64
#define NXX   512
#define NWW   512
#define TSTEP 1024
#define RCTAS 128
#define RTHR  256
#define GROUPS 4
#define GCTAS 32     // CTAs per group
#define BGS   8      // batches per group
#define ROWS  16     // rows per CTA
#define PST   136    // partial-buffer stride (floats)

typedef unsigned long long u64;

// ---------------- packed f32x2 helpers ----------------------------------------
#define FMA2(acc, w, h) asm("fma.rn.f32x2 %0, %1, %2, %0;" : "+l"(acc) : "l"(w), "l"(h))
__device__ __forceinline__ u64 dup2(float a) {
    u64 r;
    asm("mov.b64 %0, {%1, %1};" : "=l"(r) : "r"(__float_as_uint(a)));
    return r;
}

// ---------------- device scratch (__device__ globals: allocation-free) --------
__device__ float d_Cv[NWW * NXX];
__device__ float d_Dv[NWW * NUU];
__device__ float d_X[NXX * NXX];
__device__ float d_X2[NXX * NXX];
__device__ float d_T1[NXX * NXX];
__device__ float d_Ahat[NXX * NXX];
__device__ float d_Bhat[NXX * NWW];
__device__ float d_B2hat[NXX * NUU];
__device__ float d_fbhat[NXX];
__device__ float d_G1[(size_t)TSTEP * BATCH * NWW];     // [t][b][j]
__device__ float d_G2[(size_t)TSTEP * BATCH * NXX];     // [t][b][x]
__device__ float d_states[(size_t)TSTEP * BATCH * NXX]; // [t][b][x]
__device__ float d_Wb[(size_t)TSTEP * BATCH * NWW];     // [t][b][j]
__device__ float d_hbuf[2 * GROUPS * NXX * BGS];  // [parity][g][x][b8]
__device__ float d_wvec[GROUPS * NWW * BGS];      // [g][j][b8]
__device__ unsigned g_cw[GROUPS * 8 * 32];        // per-group per-octile w flags (128B pad)
__device__ unsigned g_ch[GROUPS * 8 * 32];        // per-group per-octile h flags
__device__ unsigned g_pcnt;                       // prep-gemm grid barrier

// ---------------- sync primitives ---------------------------------------------
__device__ __forceinline__ void rel_add1(unsigned* cnt) {
    asm volatile("red.release.gpu.add.u32 [%0], 1;" :: "l"(cnt) : "memory");
}
__device__ __forceinline__ void wait_cnt(unsigned* cnt, unsigned target) {
    unsigned v;
    do {
        asm volatile("ld.acquire.gpu.u32 %0, [%1];" : "=r"(v) : "l"(cnt) : "memory");
    } while (v < target);
}
__device__ __forceinline__ float4 ldcg4(const float4* p) {
    float4 v;
    asm volatile("ld.global.cg.v4.f32 {%0,%1,%2,%3}, [%4];"
                 : "=f"(v.x), "=f"(v.y), "=f"(v.z), "=f"(v.w) : "l"(p));
    return v;
}

// ---------------- prep: Cv, Dv, X0 = 2I - E, reset prep barrier ---------------
__global__ void prep_kernel(const float* __restrict__ C2, const float* __restrict__ mult,
                            const float* __restrict__ Dt, const float* __restrict__ E) {
    int i = blockIdx.x * blockDim.x + threadIdx.x;
    int stride = gridDim.x * blockDim.x;
    if (i == 0) g_pcnt = 0u;
    for (int idx = i; idx < NWW * NXX; idx += stride) {
        int r = idx / NXX;
        d_Cv[idx] = C2[idx] / mult[r];
    }
    for (int idx = i; idx < NWW * NUU; idx += stride) {
        int r = idx / NUU;
        d_Dv[idx] = Dt[idx] / mult[r];
    }
    for (int idx = i; idx < NXX * NXX; idx += stride) {
        int r = idx / NXX, c = idx % NXX;
        d_X[idx] = (r == c ? 2.0f : 0.0f) - E[idx];
    }
}

// ---------------- fused prep GEMM chain (persistent, 64 CTAs) -----------------
__device__ __forceinline__ void gemm_tile(const float* __restrict__ A, const float* __restrict__ Bm,
                                          float* __restrict__ C, int N, int K, int mode,
                                          int bx, int by,
                                          float (*As)[16][64], float (*Bs)[16][64]) {
    int tid = threadIdx.x;
    int tx = tid & 15, ty = tid >> 4;
    int ar = tid >> 2, ac = (tid & 3) << 2;
    int br = tid >> 4, bc = (tid & 15) << 2;
    const float* Aptr = A + (size_t)(by * 64 + ar) * K + ac;
    const float* Bptr = Bm + (size_t)br * N + bx * 64 + bc;

    float4 av = *(const float4*)Aptr;
    float4 bv = *(const float4*)Bptr;
    As[0][ac + 0][ar] = av.x; As[0][ac + 1][ar] = av.y;
    As[0][ac + 2][ar] = av.z; As[0][ac + 3][ar] = av.w;
    *(float4*)&Bs[0][br][bc] = bv;
    __syncthreads();

    float acc[4][4] = {};
    int buf = 0;
    for (int k0 = 16; k0 <= K; k0 += 16) {
        if (k0 < K) {
            av = *(const float4*)(Aptr + k0);
            bv = *(const float4*)(Bptr + (size_t)k0 * N);
        }
#pragma unroll
        for (int k = 0; k < 16; k++) {
            float4 a = *(const float4*)&As[buf][k][ty * 4];
            float4 b = *(const float4*)&Bs[buf][k][tx * 4];
            acc[0][0] = fmaf(a.x, b.x, acc[0][0]); acc[0][1] = fmaf(a.x, b.y, acc[0][1]);
            acc[0][2] = fmaf(a.x, b.z, acc[0][2]); acc[0][3] = fmaf(a.x, b.w, acc[0][3]);
            acc[1][0] = fmaf(a.y, b.x, acc[1][0]); acc[1][1] = fmaf(a.y, b.y, acc[1][1]);
            acc[1][2] = fmaf(a.y, b.z, acc[1][2]); acc[1][3] = fmaf(a.y, b.w, acc[1][3]);
            acc[2][0] = fmaf(a.z, b.x, acc[2][0]); acc[2][1] = fmaf(a.z, b.y, acc[2][1]);
            acc[2][2] = fmaf(a.z, b.z, acc[2][2]); acc[2][3] = fmaf(a.z, b.w, acc[2][3]);
            acc[3][0] = fmaf(a.w, b.x, acc[3][0]); acc[3][1] = fmaf(a.w, b.y, acc[3][1]);
            acc[3][2] = fmaf(a.w, b.z, acc[3][2]); acc[3][3] = fmaf(a.w, b.w, acc[3][3]);
        }
        if (k0 < K) {
            int nb = buf ^ 1;
            As[nb][ac + 0][ar] = av.x; As[nb][ac + 1][ar] = av.y;
            As[nb][ac + 2][ar] = av.z; As[nb][ac + 3][ar] = av.w;
            *(float4*)&Bs[nb][br][bc] = bv;
        }
        __syncthreads();
        buf ^= 1;
    }
#pragma unroll
    for (int i = 0; i < 4; i++) {
        int r = by * 64 + ty * 4 + i;
        float o[4];
#pragma unroll
        for (int j = 0; j < 4; j++) {
            int cx = bx * 64 + tx * 4 + j;
            float v = acc[i][j];
            if (mode) v = (r == cx ? 2.0f : 0.0f) - v;
            o[j] = v;
        }
        *(float4*)&C[(size_t)r * N + bx * 64 + tx * 4] = make_float4(o[0], o[1], o[2], o[3]);
    }
}

__device__ __forceinline__ void gbar(unsigned gen) {
    __threadfence();
    __syncthreads();
    if (threadIdx.x == 0) {
        rel_add1(&g_pcnt);
        wait_cnt(&g_pcnt, 64u * gen);
    }
    __syncthreads();
}

__global__ void __launch_bounds__(256, 1) prepgemm_kernel(
        const float* __restrict__ E, const float* __restrict__ F_w,
        const float* __restrict__ F_b, const float* __restrict__ B1_w,
        const float* __restrict__ B2_w) {
    __shared__ float As[2][16][64];
    __shared__ float Bs[2][16][64];
    int cta = blockIdx.x;
    int bx = cta & 7, by = cta >> 3;

    // Newton-Schulz: 3 iterations, X0 in d_X
    gemm_tile(E, d_X, d_T1, 512, 512, 1, bx, by, As, Bs);  gbar(1);
    gemm_tile(d_X, d_T1, d_X2, 512, 512, 0, bx, by, As, Bs); gbar(2);
    gemm_tile(E, d_X2, d_T1, 512, 512, 1, bx, by, As, Bs); gbar(3);
    gemm_tile(d_X2, d_T1, d_X, 512, 512, 0, bx, by, As, Bs); gbar(4);
    gemm_tile(E, d_X, d_T1, 512, 512, 1, bx, by, As, Bs);  gbar(5);
    gemm_tile(d_X, d_T1, d_X2, 512, 512, 0, bx, by, As, Bs); gbar(6);
    // d_X2 = Einv
    gemm_tile(d_X2, F_w, d_Ahat, 512, 512, 0, bx, by, As, Bs);
    gemm_tile(d_X2, B1_w, d_Bhat, 512, 512, 0, bx, by, As, Bs);
    if (cta < 8) {
        gemm_tile(d_X2, B2_w, d_B2hat, 64, 512, 0, 0, cta, As, Bs);
    } else if (cta < 16 && threadIdx.x < 64) {
        int r = (cta - 8) * 64 + threadIdx.x;
        float s = 0.f;
        for (int k = 0; k < NXX; k++) s = fmaf(d_X2[(size_t)r * NXX + k], F_b[k], s);
        d_fbhat[r] = s;
    }
}

// ---------------- u projections: out[(t*B + b)*J + j] -------------------------
__global__ void uproj_kernel(const float* __restrict__ u, const float* __restrict__ M,
                             const float* __restrict__ bias, float* __restrict__ out, int J) {
    __shared__ float U_s[NUU][65];
    __shared__ float M_s[64][65];
    int tid = threadIdx.x;
    int j0 = blockIdx.x * 64, t0 = blockIdx.y * 64, b = blockIdx.z;
    for (int i = tid; i < 64 * 64; i += 256) {
        int kk = i >> 6, tt = i & 63;
        U_s[kk][tt] = u[(size_t)b * NUU * TSTEP + (size_t)kk * TSTEP + t0 + tt];
    }
    for (int i = tid; i < 64 * 64; i += 256) {
        int j = i >> 6, k = i & 63;
        M_s[j][k] = M[(size_t)(j0 + j) * NUU + k];
    }
    __syncthreads();
    int lane = tid & 31, wg = tid >> 5;
    float acc0[8] = {}, acc1[8] = {};
    for (int k = 0; k < 64; k++) {
        float u0 = U_s[k][lane], u1 = U_s[k][lane + 32];
#pragma unroll
        for (int j = 0; j < 8; j++) {
            float m = M_s[wg * 8 + j][k];
            acc0[j] = fmaf(u0, m, acc0[j]);
            acc1[j] = fmaf(u1, m, acc1[j]);
        }
    }
    int jj0 = j0 + wg * 8;
    float bsv[8];
#pragma unroll
    for (int j = 0; j < 8; j++) bsv[j] = bias[jj0 + j];
    size_t r0 = ((size_t)(t0 + lane) * BATCH + b) * J + jj0;
    size_t r1 = ((size_t)(t0 + lane + 32) * BATCH + b) * J + jj0;
    *(float4*)&out[r0]     = make_float4(acc0[0] + bsv[0], acc0[1] + bsv[1], acc0[2] + bsv[2], acc0[3] + bsv[3]);
    *(float4*)&out[r0 + 4] = make_float4(acc0[4] + bsv[4], acc0[5] + bsv[5], acc0[6] + bsv[6], acc0[7] + bsv[7]);
    *(float4*)&out[r1]     = make_float4(acc1[0] + bsv[0], acc1[1] + bsv[1], acc1[2] + bsv[2], acc1[3] + bsv[3]);
    *(float4*)&out[r1 + 4] = make_float4(acc1[4] + bsv[4], acc1[5] + bsv[5], acc1[6] + bsv[6], acc1[7] + bsv[7]);
}

// ---------------- init --------------------------------------------------------
__global__ void init_kernel() {
    int i = blockIdx.x * blockDim.x + threadIdx.x;
    int stride = gridDim.x * blockDim.x;
    for (int idx = i; idx < GROUPS * 8 * 32; idx += stride) {
        g_cw[idx] = 0u;
        g_ch[idx] = 0u;
    }
    for (int idx = i; idx < 2 * GROUPS * NXX * BGS; idx += stride) d_hbuf[idx] = 0.f;
    for (int idx = i; idx < BATCH * NXX; idx += stride) d_states[idx] = 0.f;  // t=0
}

// ---------------- f32x2 dot: 8 row-pairs x 16 k (interleaved), one batch col --
// hp = h_s + b (stride BGS per k); wkb = [k][16 rows] f32; acc = 8 u64 row-pairs
__device__ __forceinline__ void dotp2(const float* __restrict__ hp,
                                      const float* __restrict__ wkb,
                                      int kbase, u64* __restrict__ acc) {
#pragma unroll
    for (int i = 0; i < 16; i++) {
        int k = kbase + 4 * i;
        u64 h2 = dup2(hp[k * BGS]);
        const ulonglong2* wp = (const ulonglong2*)(wkb + k * ROWS);
        ulonglong2 w01 = wp[0], w23 = wp[1], w45 = wp[2], w67 = wp[3];
        FMA2(acc[0], w01.x, h2); FMA2(acc[1], w01.y, h2);
        FMA2(acc[2], w23.x, h2); FMA2(acc[3], w23.y, h2);
        FMA2(acc[4], w45.x, h2); FMA2(acc[5], w45.y, h2);
        FMA2(acc[6], w67.x, h2); FMA2(acc[7], w67.y, h2);
    }
}

// ---------------- persistent sequential recurrence (dataflow flags) -----------
// 4 groups x 32 CTAs; group g: batches [8g, 8g+8); CTA: 16 rows.
// Per-octile flags: consumer warp w depends only on CTAs [4w, 4w+4) of its group.
__global__ void __launch_bounds__(RTHR, 1) recur_kernel() {
    extern __shared__ float sm[];
    float* wC  = sm;                 // [512][16]
    float* wA  = wC + 8192;
    float* wB  = wA + 8192;
    float* h_s = wB + 8192;          // [512][8]
    float* w_s = h_s + NXX * BGS;    // [512][8]
    float* pW  = w_s + NWW * BGS;    // [32][PST]  outputs at b*16+row
    float* pA  = pW + 32 * PST;
    float* pB  = pA + 32 * PST;

    int tid  = threadIdx.x;
    int cta  = blockIdx.x;
    int g    = cta >> 5;
    int lc   = cta & 31;
    int j0   = lc * ROWS;
    int warp = tid >> 5, lane = tid & 31;
    int kh = lane >> 3, b = lane & 7;
    int rrow = tid & 15, rb = tid >> 4;        // reduce mapping (tid<128): coalesced rows
    int bb = g * BGS + rb;

    unsigned* cw_arr = &g_cw[(g * 8 + (lc >> 2)) * 32];   // my arrive flag (w)
    unsigned* ch_arr = &g_ch[(g * 8 + (lc >> 2)) * 32];   // my arrive flag (h)
    unsigned* cw_poll = &g_cw[(g * 8 + warp) * 32];       // my warp's dependency (w)
    unsigned* ch_poll = &g_ch[(g * 8 + warp) * 32];       // my warp's dependency (h)

    float* wg = d_wvec + g * NWW * BGS;

    // stage weight slices [k][row] (resident for whole kernel)
    for (int i = tid; i < 8192; i += RTHR) {
        int k = i >> 4, c = i & 15;
        wC[i] = d_Cv[(size_t)(j0 + c) * NXX + k];
        wA[i] = d_Ahat[(size_t)(j0 + c) * NXX + k];
        wB[i] = d_Bhat[(size_t)(j0 + c) * NWW + k];
    }
    __syncthreads();

    int kbase = warp * 64 + kh;
    int slot = warp * 4 + kh;
    // partial outputs: u64 row-pair r at f32 index b*16 + 2r  (u64 index b*8 + r)
    u64* ppW = (u64*)(pW + slot * PST + b * 16);
    u64* ppA = (u64*)(pA + slot * PST + b * 16);
    u64* ppB = (u64*)(pB + slot * PST + b * 16);
    int roff = rb * 16 + rrow;   // partial-buffer f32 output index (== tid for tid<128)

    for (int t = 0; t < TSTEP; t++) {
        // prefetch G terms (in flight during poll)
        float g1 = 0.f, g2 = 0.f;
        if (tid < 128) {
            g1 = __ldcg(&d_G1[((size_t)t * BATCH + bb) * NWW + j0 + rrow]);
            if (t < TSTEP - 1)
                g2 = __ldcg(&d_G2[((size_t)t * BATCH + bb) * NXX + j0 + rrow]);
        }
        // wait for this warp's h(t) octile, copy it
        if (t > 0) {
            if (lane == 0) wait_cnt(ch_poll, 512u * (unsigned)t);
            __syncwarp();
        }
        {
            const float4* src = (const float4*)(d_hbuf +
                ((size_t)(t & 1) * GROUPS + g) * (NXX * BGS)) + warp * 128;
            float4* dst = (float4*)h_s + warp * 128;
#pragma unroll
            for (int i = 0; i < 4; i++) dst[lane + 32 * i] = ldcg4(&src[lane + 32 * i]);
        }
        __syncwarp();
        // phase A: Cv @ h  (f32x2 over row pairs)
        {
            u64 acc[8] = {};
            dotp2(h_s + b, wC, kbase, acc);
#pragma unroll
            for (int r = 0; r < 8; r++) ppW[r] = acc[r];
        }
        __syncthreads();  // #1: pW complete
        if (tid < 128) {
            float v = g1;
#pragma unroll
            for (int p = 0; p < 32; p++) v += pW[p * PST + roff];
            v = fmaxf(v, 0.f);
            wg[(j0 + rrow) * BGS + rb] = v;
            d_Wb[((size_t)t * BATCH + bb) * NWW + j0 + rrow] = v;
            rel_add1(cw_arr);   // this thread's own w store is release-ordered
        }
        if (t == TSTEP - 1) break;
        // Ahat @ h (independent of w — overlaps other CTAs' phase A)
        {
            u64 acc[8] = {};
            dotp2(h_s + b, wA, kbase, acc);
#pragma unroll
            for (int r = 0; r < 8; r++) ppA[r] = acc[r];
        }
        // wait for this warp's w(t) octile, copy it
        if (lane == 0) wait_cnt(cw_poll, 512u * (unsigned)(t + 1));
        __syncwarp();
        {
            const float4* src = (const float4*)wg + warp * 128;
            float4* dst = (float4*)w_s + warp * 128;
#pragma unroll
            for (int i = 0; i < 4; i++) dst[lane + 32 * i] = ldcg4(&src[lane + 32 * i]);
        }
        __syncwarp();
        // Bhat @ w
        {
            u64 acc[8] = {};
            dotp2(w_s + b, wB, kbase, acc);
#pragma unroll
            for (int r = 0; r < 8; r++) ppB[r] = acc[r];
        }
        __syncthreads();  // #2: pA, pB complete
        if (tid < 128) {
            float v = g2;
#pragma unroll
            for (int p = 0; p < 32; p++)
                v += pA[p * PST + roff] + pB[p * PST + roff];
            d_hbuf[((size_t)((t + 1) & 1) * GROUPS + g) * (NXX * BGS) + (j0 + rrow) * BGS + rb] = v;
            d_states[((size_t)(t + 1) * BATCH + bb) * NXX + j0 + rrow] = v;
            rel_add1(ch_arr);
        }
    }
}

// ---------------- epilogue: y = states@C1.T + W@D11.T + u@D12.T + by ----------
__global__ void yfinal_kernel(const float* __restrict__ u, const float* __restrict__ C1,
                              const float* __restrict__ D11, const float* __restrict__ D12,
                              const float* __restrict__ by, float* __restrict__ out) {
    __shared__ float As[64][65];
    __shared__ float Bs[64][68];
    int tid = threadIdx.x;
    int tx = tid & 15, ty = tid >> 4;
    int t0 = blockIdx.x * 64, b = blockIdx.y;
    float acc[4][4] = {};
    for (int seg = 0; seg < 3; seg++) {
        int nchunk = (seg == 2) ? 1 : 8;
        const float* Am = (seg == 0) ? C1 : (seg == 1) ? D11 : D12;
        int Ksz = (seg == 2) ? 64 : 512;
        for (int ch = 0; ch < nchunk; ch++) {
            int x0 = ch * 64;
            for (int i = tid; i < 64 * 64; i += 256) {
                int j = i >> 6, k = i & 63;
                As[j][k] = Am[(size_t)j * Ksz + x0 + k];
            }
            if (seg == 2) {
                for (int i = tid; i < 64 * 64; i += 256) {
                    int k = i >> 6, tt = i & 63;
                    Bs[k][tt] = u[((size_t)b * NUU + k) * TSTEP + t0 + tt];
                }
            } else {
                const float* S = (seg == 0) ? d_states : d_Wb;
                for (int i = tid; i < 64 * 64; i += 256) {
                    int tt = i >> 6, xx = i & 63;
                    Bs[xx][tt] = S[((size_t)(t0 + tt) * BATCH + b) * 512 + x0 + xx];
                }
            }
            __syncthreads();
#pragma unroll 8
            for (int k = 0; k < 64; k++) {
                float a0 = As[ty * 4 + 0][k];
                float a1 = As[ty * 4 + 1][k];
                float a2 = As[ty * 4 + 2][k];
                float a3 = As[ty * 4 + 3][k];
                float4 bv = *(const float4*)&Bs[k][tx * 4];
                acc[0][0] = fmaf(a0, bv.x, acc[0][0]); acc[0][1] = fmaf(a0, bv.y, acc[0][1]);
                acc[0][2] = fmaf(a0, bv.z, acc[0][2]); acc[0][3] = fmaf(a0, bv.w, acc[0][3]);
                acc[1][0] = fmaf(a1, bv.x, acc[1][0]); acc[1][1] = fmaf(a1, bv.y, acc[1][1]);
                acc[1][2] = fmaf(a1, bv.z, acc[1][2]); acc[1][3] = fmaf(a1, bv.w, acc[1][3]);
                acc[2][0] = fmaf(a2, bv.x, acc[2][0]); acc[2][1] = fmaf(a2, bv.y, acc[2][1]);
                acc[2][2] = fmaf(a2, bv.z, acc[2][2]); acc[2][3] = fmaf(a2, bv.w, acc[2][3]);
                acc[3][0] = fmaf(a3, bv.x, acc[3][0]); acc[3][1] = fmaf(a3, bv.y, acc[3][1]);
                acc[3][2] = fmaf(a3, bv.z, acc[3][2]); acc[3][3] = fmaf(a3, bv.w, acc[3][3]);
            }
            __syncthreads();
        }
    }
#pragma unroll
    for (int i = 0; i < 4; i++) {
        int j = ty * 4 + i;
        float bj = by[j];
        float4 o = make_float4(acc[i][0] + bj, acc[i][1] + bj, acc[i][2] + bj, acc[i][3] + bj);
        *(float4*)&out[((size_t)b * NYY + j) * TSTEP + t0 + tx * 4] = o;
    }
}

// ---------------- launch ------------------------------------------------------
extern "C" void kernel_launch(void* const* d_in, const int* in_sizes, int n_in,
                              void* d_out, int out_size) {
    const float* u      = (const float*)d_in[0];
    const float* E      = (const float*)d_in[1];
    const float* F_w    = (const float*)d_in[2];
    const float* F_b    = (const float*)d_in[3];
    const float* B1_w   = (const float*)d_in[4];
    const float* B2_w   = (const float*)d_in[5];
    const float* C2tild = (const float*)d_in[6];
    const float* bv     = (const float*)d_in[7];
    const float* Dtild  = (const float*)d_in[8];
    const float* C1_w   = (const float*)d_in[9];
    const float* D11_w  = (const float*)d_in[10];
    const float* D12_w  = (const float*)d_in[11];
    const float* by     = (const float*)d_in[12];
    const float* multis = (const float*)d_in[13];
    float* out = (float*)d_out;

    float *Dv, *G1, *G2, *B2hat, *fbhat;
    cudaGetSymbolAddress((void**)&Dv,    d_Dv);
    cudaGetSymbolAddress((void**)&G1,    d_G1);
    cudaGetSymbolAddress((void**)&G2,    d_G2);
    cudaGetSymbolAddress((void**)&B2hat, d_B2hat);
    cudaGetSymbolAddress((void**)&fbhat, d_fbhat);

    const int SMEM_RECUR = (3 * 8192 + 2 * 4096 + 3 * 32 * PST) * 4;
    cudaFuncSetAttribute(recur_kernel, cudaFuncAttributeMaxDynamicSharedMemorySize, SMEM_RECUR);

    // 1) Cv, Dv, X0 = 2I - E, reset prep barrier
    prep_kernel<<<256, 256>>>(C2tild, multis, Dtild, E);
    // 2) fused Newton-Schulz (3 iters) + weight folding
    prepgemm_kernel<<<64, 256>>>(E, F_w, F_b, B1_w, B2_w);
    // 3,4) input-driven terms
    uproj_kernel<<<dim3(8, 16, 32), 256>>>(u, Dv, bv, G1, NWW);
    uproj_kernel<<<dim3(8, 16, 32), 256>>>(u, B2hat, fbhat, G2, NXX);
    // 5) init flags + state
    init_kernel<<<64, 256>>>();
    // 6) sequential recurrence
    recur_kernel<<<RCTAS, RTHR, SMEM_RECUR>>>();
    // 7) epilogue
    yfinal_kernel<<<dim3(16, 32), 256>>>(u, C1_w, D11_w, D12_w, by, out);
}